// round 6
// baseline (speedup 1.0000x reference)
#include <cuda_runtime.h>

// LinearAttentionTriton:
//   M_t = K_t^T V_t   (64x64 per trunk)     -- kA (staged, split-K x2, 256 thr, 32 KB)
//   S   = sum_t M_t^T (64x64 global)        -- kB1/kB2 (deterministic)
//   out_t = (Q_t @ M_t) @ S                 -- kQO (fused, 256 thr, 48 KB)
// N = 262144, D = 64, TRUNK = 128, T = 2048. 2.68e9 MACs total.

#define D 64
#define TRUNK 128
#define T_TRUNKS 2048
#define B1_BLOCKS 128

__device__ __align__(16) float g_S[D * D];
__device__ __align__(16) float g_part[T_TRUNKS * D * D];   // M_t, 33.5 MB
__device__ __align__(16) float g_red[B1_BLOCKS * D * D];

// ---------------- f32x2 helpers ----------------
__device__ __forceinline__ unsigned long long bcast2(float x) {
    unsigned long long r;
    asm("mov.b64 %0, {%1, %1};" : "=l"(r) : "f"(x));
    return r;
}
__device__ __forceinline__ void f2(unsigned long long& d,
                                   unsigned long long a,
                                   unsigned long long b) {
    asm("fma.rn.f32x2 %0, %1, %2, %0;" : "+l"(d) : "l"(a), "l"(b));
}
__device__ __forceinline__ void a2(unsigned long long& d, unsigned long long a) {
    asm("add.rn.f32x2 %0, %0, %1;" : "+l"(d) : "l"(a));
}

// ---------------- kA: M_t = K_t^T V_t ----------------
// grid 2048, block 256, static smem 32 KB. Two 64-row stages; within a stage
// halves h=0/1 take 32 K-rows each (split-K). 4x8 tile per thread.
__global__ void __launch_bounds__(256, 3) kA(const float* __restrict__ Kg,
                                             const float* __restrict__ Vg) {
    __shared__ float sK[64 * 64];
    __shared__ float sV[64 * 64];

    const int tid = threadIdx.x;
    const long t = blockIdx.x;

    const int h  = tid >> 7;         // 0/1
    const int lt = tid & 127;
    const int d0 = (lt >> 3) * 4;    // 32 groups * 4 = 64 rows of M
    const int e0 = (lt & 7) * 8;     // 8 groups * 8 = 64 cols

    unsigned long long acc[4][4];
#pragma unroll
    for (int i = 0; i < 4; ++i)
#pragma unroll
        for (int j = 0; j < 4; ++j) acc[i][j] = 0ull;

#pragma unroll
    for (int s = 0; s < 2; ++s) {
        const float4* K4 = (const float4*)Kg + t * 2048 + s * 1024;
        const float4* V4 = (const float4*)Vg + t * 2048 + s * 1024;
#pragma unroll
        for (int i = tid; i < 1024; i += 256) {
            ((float4*)sK)[i] = K4[i];
            ((float4*)sV)[i] = V4[i];
        }
        __syncthreads();

        const int rbase = h * 32;
#pragma unroll 4
        for (int rr = 0; rr < 32; ++rr) {
            const int r = rbase + rr;
            const float4 a = *(const float4*)&sK[r * 64 + d0];
            const ulonglong2 b01 = *(const ulonglong2*)&sV[r * 64 + e0];
            const ulonglong2 b23 = *(const ulonglong2*)&sV[r * 64 + e0 + 4];
            const unsigned long long pb[4] = {b01.x, b01.y, b23.x, b23.y};
            const float av[4] = {a.x, a.y, a.z, a.w};
#pragma unroll
            for (int i = 0; i < 4; ++i) {
                const unsigned long long pa = bcast2(av[i]);
                f2(acc[i][0], pa, pb[0]); f2(acc[i][1], pa, pb[1]);
                f2(acc[i][2], pa, pb[2]); f2(acc[i][3], pa, pb[3]);
            }
        }
        __syncthreads();
    }

    // merge halves: h==1 parks its 64x64 partial in sK, h==0 adds + writes out
    if (h == 1) {
#pragma unroll
        for (int i = 0; i < 4; ++i) {
            *(ulonglong2*)&sK[(d0 + i) * 64 + e0]     = make_ulonglong2(acc[i][0], acc[i][1]);
            *(ulonglong2*)&sK[(d0 + i) * 64 + e0 + 4] = make_ulonglong2(acc[i][2], acc[i][3]);
        }
    }
    __syncthreads();
    if (h == 0) {
        float* dst = g_part + t * 4096;
#pragma unroll
        for (int i = 0; i < 4; ++i) {
            const ulonglong2 v0 = *(const ulonglong2*)&sK[(d0 + i) * 64 + e0];
            const ulonglong2 v1 = *(const ulonglong2*)&sK[(d0 + i) * 64 + e0 + 4];
            a2(acc[i][0], v0.x); a2(acc[i][1], v0.y);
            a2(acc[i][2], v1.x); a2(acc[i][3], v1.y);
            *(ulonglong2*)&dst[(d0 + i) * 64 + e0]     = make_ulonglong2(acc[i][0], acc[i][1]);
            *(ulonglong2*)&dst[(d0 + i) * 64 + e0 + 4] = make_ulonglong2(acc[i][2], acc[i][3]);
        }
    }
}

// ---------------- kB1/kB2: deterministic reduction to S ----------------
__global__ void __launch_bounds__(256) kB1() {
    const int blk = blockIdx.x;
    const int tid = threadIdx.x;
    const float* src = g_part + (long)blk * 16 * 4096;
#pragma unroll
    for (int i = 0; i < 16; ++i) {
        const int x = tid + i * 256;
        float s = 0.0f;
#pragma unroll
        for (int tt = 0; tt < 16; ++tt) s += src[tt * 4096 + x];
        g_red[blk * 4096 + x] = s;
    }
}
__global__ void __launch_bounds__(256) kB2() {
    const int idx = blockIdx.x * 256 + threadIdx.x;   // idx = e*64+d
    const int d = idx & 63, e = idx >> 6;
    float s = 0.0f;
#pragma unroll 8
    for (int b = 0; b < B1_BLOCKS; ++b) s += g_red[b * 4096 + idx];
    g_S[d * 64 + e] = s;
}

// ---------------- kQO: out_t = (Q_t @ M_t) @ S ----------------
// grid 2048, block 256, dyn smem 48 KB. 4x8 tile per thread.
// sQ XOR-swizzled (also holds P swizzled). sMS holds M, then S.
__global__ void __launch_bounds__(256, 3) kQO(const float* __restrict__ Qg,
                                              float* __restrict__ outg) {
    extern __shared__ float smQ[];
    float* sQ  = smQ;           // 128*64 swizzled
    float* sMS = smQ + 8192;    // 64*64: M, then S

    const int tid = threadIdx.x;
    const long t = blockIdx.x;

    const float4* M4 = (const float4*)g_part + t * 1024;
#pragma unroll
    for (int i = tid; i < 1024; i += 256)
        ((float4*)sMS)[i] = M4[i];

    const float4* Q4 = (const float4*)Qg + t * 2048;
#pragma unroll
    for (int i = tid; i < 2048; i += 256) {
        const float4 v = Q4[i];
        const int row = i >> 4;
        const int col = (i & 15) << 2;
        const int sw = ((row >> 3) & 7) << 2;
        *(float4*)&sQ[row * 64 + (col ^ sw)] = v;   // (col+j)^sw == (col^sw)+j, j<4
    }
    __syncthreads();

    const int r0 = (tid >> 3) * 4;   // 32 groups * 4 = 128 rows
    const int c0 = (tid & 7) * 8;    // 8 groups * 8 = 64 cols
    const int sw = ((r0 >> 3) & 7) << 2;   // r0..r0+3 share one 8-row block

    unsigned long long acc[4][4];
#pragma unroll
    for (int i = 0; i < 4; ++i)
#pragma unroll
        for (int j = 0; j < 4; ++j) acc[i][j] = 0ull;

    // ---- GEMM1: P = Q_t @ M_t ----
#pragma unroll 2
    for (int k0 = 0; k0 < 64; k0 += 4) {
        float a[4][4];
#pragma unroll
        for (int i = 0; i < 4; ++i)
            *(float4*)a[i] = *(const float4*)&sQ[(r0 + i) * 64 + (k0 ^ sw)];
#pragma unroll
        for (int j = 0; j < 4; ++j) {
            const ulonglong2 b01 = *(const ulonglong2*)&sMS[(k0 + j) * 64 + c0];
            const ulonglong2 b23 = *(const ulonglong2*)&sMS[(k0 + j) * 64 + c0 + 4];
            const unsigned long long pb[4] = {b01.x, b01.y, b23.x, b23.y};
#pragma unroll
            for (int i = 0; i < 4; ++i) {
                const unsigned long long pa = bcast2(a[i][j]);
                f2(acc[i][0], pa, pb[0]); f2(acc[i][1], pa, pb[1]);
                f2(acc[i][2], pa, pb[2]); f2(acc[i][3], pa, pb[3]);
            }
        }
    }
    __syncthreads();   // all sQ/sMS reads complete

    // store P swizzled into sQ; refill sMS with S
#pragma unroll
    for (int i = 0; i < 4; ++i) {
        float4 p0, p1;
        *(ulonglong2*)&p0 = make_ulonglong2(acc[i][0], acc[i][1]);
        *(ulonglong2*)&p1 = make_ulonglong2(acc[i][2], acc[i][3]);
        const int row = r0 + i;
        *(float4*)&sQ[row * 64 + (c0 ^ sw)]       = p0;
        *(float4*)&sQ[row * 64 + ((c0 + 4) ^ sw)] = p1;
    }
#pragma unroll
    for (int j = 0; j < 4; ++j)
        ((float4*)sMS)[tid + j * 256] = ((const float4*)g_S)[tid + j * 256];
    __syncthreads();

    // ---- GEMM2: out = P @ S ----
#pragma unroll
    for (int i = 0; i < 4; ++i)
#pragma unroll
        for (int j = 0; j < 4; ++j) acc[i][j] = 0ull;

#pragma unroll 2
    for (int k0 = 0; k0 < 64; k0 += 4) {
        float a[4][4];
#pragma unroll
        for (int i = 0; i < 4; ++i)
            *(float4*)a[i] = *(const float4*)&sQ[(r0 + i) * 64 + (k0 ^ sw)];
#pragma unroll
        for (int j = 0; j < 4; ++j) {
            const ulonglong2 b01 = *(const ulonglong2*)&sMS[(k0 + j) * 64 + c0];
            const ulonglong2 b23 = *(const ulonglong2*)&sMS[(k0 + j) * 64 + c0 + 4];
            const unsigned long long pb[4] = {b01.x, b01.y, b23.x, b23.y};
#pragma unroll
            for (int i = 0; i < 4; ++i) {
                const unsigned long long pa = bcast2(a[i][j]);
                f2(acc[i][0], pa, pb[0]); f2(acc[i][1], pa, pb[1]);
                f2(acc[i][2], pa, pb[2]); f2(acc[i][3], pa, pb[3]);
            }
        }
    }

    float* outp = outg + t * (TRUNK * D);
#pragma unroll
    for (int i = 0; i < 4; ++i) {
        *(ulonglong2*)&outp[(r0 + i) * 64 + c0]     = make_ulonglong2(acc[i][0], acc[i][1]);
        *(ulonglong2*)&outp[(r0 + i) * 64 + c0 + 4] = make_ulonglong2(acc[i][2], acc[i][3]);
    }
}

#define SMEM_QO_BYTES ((8192 + 4096) * 4)        // 49152

extern "C" void kernel_launch(void* const* d_in, const int* in_sizes, int n_in,
                              void* d_out, int out_size) {
    const float* Q = (const float*)d_in[0];
    const float* K = (const float*)d_in[1];
    const float* V = (const float*)d_in[2];
    float* out = (float*)d_out;

    cudaFuncSetAttribute(kQO, cudaFuncAttributeMaxDynamicSharedMemorySize, SMEM_QO_BYTES);

    kA<<<T_TRUNKS, 256>>>(K, V);
    kB1<<<B1_BLOCKS, 256>>>();
    kB2<<<16, 256>>>();
    kQO<<<T_TRUNKS, 256, SMEM_QO_BYTES>>>(Q, out);
}

// round 7
// speedup vs baseline: 1.5739x; 1.5739x over previous
#include <cuda_runtime.h>

// LinearAttentionTriton:
//   M_t = K_t^T V_t   (64x64 per trunk)     -- kA (128 thr, 8x8 tile, staged 32 KB)
//   S   = sum_t M_t^T (64x64 global)        -- kB1/kB2 (deterministic)
//   out_t = (Q_t @ M_t) @ S                 -- kQO (128 thr, 8x8 tile, 48 KB) [round-5]
// N = 262144, D = 64, TRUNK = 128, T = 2048. 2.68e9 MACs total.

#define D 64
#define TRUNK 128
#define T_TRUNKS 2048
#define B1_BLOCKS 128

__device__ __align__(16) float g_S[D * D];
__device__ __align__(16) float g_part[T_TRUNKS * D * D];   // M_t, 33.5 MB
__device__ __align__(16) float g_red[B1_BLOCKS * D * D];

// ---------------- f32x2 helpers ----------------
__device__ __forceinline__ unsigned long long bcast2(float x) {
    unsigned long long r;
    asm("mov.b64 %0, {%1, %1};" : "=l"(r) : "f"(x));
    return r;
}
__device__ __forceinline__ void f2(unsigned long long& d,
                                   unsigned long long a,
                                   unsigned long long b) {
    asm("fma.rn.f32x2 %0, %1, %2, %0;" : "+l"(d) : "l"(a), "l"(b));
}
__device__ __forceinline__ void a2(unsigned long long& d, unsigned long long a) {
    asm("add.rn.f32x2 %0, %0, %1;" : "+l"(d) : "l"(a));
}

// ---------------- kA: M_t = K_t^T V_t ----------------
// grid 2048, block 128, static smem 32 KB. Two 64-row stages; within each
// stage halves h=0/1 take 32 K-rows (split-K). 8x8 tile per thread (64 thr
// cover the 64x64 output). Reg accumulation across stages; smem merge at end.
__global__ void __launch_bounds__(128, 5) kA(const float* __restrict__ Kg,
                                             const float* __restrict__ Vg) {
    __shared__ float sK[64 * 64];
    __shared__ float sV[64 * 64];

    const int tid = threadIdx.x;
    const long t = blockIdx.x;

    const int h  = tid >> 6;         // 0/1: rows [h*32, h*32+32) of each stage
    const int lt = tid & 63;
    const int d0 = (lt >> 3) * 8;
    const int e0 = (lt & 7) * 8;

    unsigned long long acc[8][4];
#pragma unroll
    for (int i = 0; i < 8; ++i)
#pragma unroll
        for (int j = 0; j < 4; ++j) acc[i][j] = 0ull;

#pragma unroll
    for (int s = 0; s < 2; ++s) {
        const float4* K4 = (const float4*)Kg + t * 2048 + s * 1024;
        const float4* V4 = (const float4*)Vg + t * 2048 + s * 1024;
#pragma unroll
        for (int i = tid; i < 1024; i += 128) {
            ((float4*)sK)[i] = K4[i];
            ((float4*)sV)[i] = V4[i];
        }
        __syncthreads();

        const int rbase = h * 32;
#pragma unroll 4
        for (int rr = 0; rr < 32; ++rr) {
            const int r = rbase + rr;
            const float4 a03 = *(const float4*)&sK[r * 64 + d0];
            const float4 a47 = *(const float4*)&sK[r * 64 + d0 + 4];
            const ulonglong2 b01 = *(const ulonglong2*)&sV[r * 64 + e0];
            const ulonglong2 b23 = *(const ulonglong2*)&sV[r * 64 + e0 + 4];
            const unsigned long long pb[4] = {b01.x, b01.y, b23.x, b23.y};
            const float av[8] = {a03.x, a03.y, a03.z, a03.w,
                                 a47.x, a47.y, a47.z, a47.w};
#pragma unroll
            for (int i = 0; i < 8; ++i) {
                const unsigned long long pa = bcast2(av[i]);
                f2(acc[i][0], pa, pb[0]); f2(acc[i][1], pa, pb[1]);
                f2(acc[i][2], pa, pb[2]); f2(acc[i][3], pa, pb[3]);
            }
        }
        __syncthreads();
    }

    // merge halves via sK (dead): h==1 parks, h==0 adds + writes out
    if (h == 1) {
#pragma unroll
        for (int i = 0; i < 8; ++i) {
            *(ulonglong2*)&sK[(d0 + i) * 64 + e0]     = make_ulonglong2(acc[i][0], acc[i][1]);
            *(ulonglong2*)&sK[(d0 + i) * 64 + e0 + 4] = make_ulonglong2(acc[i][2], acc[i][3]);
        }
    }
    __syncthreads();
    if (h == 0) {
        float* dst = g_part + t * 4096;
#pragma unroll
        for (int i = 0; i < 8; ++i) {
            const ulonglong2 v0 = *(const ulonglong2*)&sK[(d0 + i) * 64 + e0];
            const ulonglong2 v1 = *(const ulonglong2*)&sK[(d0 + i) * 64 + e0 + 4];
            a2(acc[i][0], v0.x); a2(acc[i][1], v0.y);
            a2(acc[i][2], v1.x); a2(acc[i][3], v1.y);
            *(ulonglong2*)&dst[(d0 + i) * 64 + e0]     = make_ulonglong2(acc[i][0], acc[i][1]);
            *(ulonglong2*)&dst[(d0 + i) * 64 + e0 + 4] = make_ulonglong2(acc[i][2], acc[i][3]);
        }
    }
}

// ---------------- kB1/kB2: deterministic reduction to S ----------------
__global__ void __launch_bounds__(256) kB1() {
    const int blk = blockIdx.x;
    const int tid = threadIdx.x;
    const float* src = g_part + (long)blk * 16 * 4096;
#pragma unroll
    for (int i = 0; i < 16; ++i) {
        const int x = tid + i * 256;
        float s = 0.0f;
#pragma unroll
        for (int tt = 0; tt < 16; ++tt) s += src[tt * 4096 + x];
        g_red[blk * 4096 + x] = s;
    }
}
__global__ void __launch_bounds__(256) kB2() {
    const int idx = blockIdx.x * 256 + threadIdx.x;   // idx = e*64+d
    const int d = idx & 63, e = idx >> 6;
    float s = 0.0f;
#pragma unroll 8
    for (int b = 0; b < B1_BLOCKS; ++b) s += g_red[b * 4096 + idx];
    g_S[d * 64 + e] = s;
}

// ---------------- kQO: out_t = (Q_t @ M_t) @ S  [round-5 verbatim] ----------------
// grid 2048, block 128, smem 48 KB (4 CTAs/SM -> 16 warps). 8x8 tile.
__global__ void __launch_bounds__(128, 4) kQO(const float* __restrict__ Qg,
                                              float* __restrict__ outg) {
    extern __shared__ float smQ[];
    float* sQ  = smQ;           // 128*64 swizzled (later holds P swizzled)
    float* sMS = smQ + 8192;    // 64*64: M, then S

    const int tid = threadIdx.x;
    const long t = blockIdx.x;

    const float4* M4 = (const float4*)g_part + t * 1024;
#pragma unroll
    for (int i = tid; i < 1024; i += 128)
        ((float4*)sMS)[i] = M4[i];

    const float4* Q4 = (const float4*)Qg + t * 2048;
#pragma unroll
    for (int i = tid; i < 2048; i += 128) {
        const float4 v = Q4[i];
        const int row = i >> 4;
        const int col = (i & 15) << 2;
        const int sw = ((row >> 3) & 7) << 2;
        *(float4*)&sQ[row * 64 + (col ^ sw)] = v;   // (col+j)^sw == (col^sw)+j
    }
    __syncthreads();

    const int r0 = (tid >> 3) * 8;   // 16 groups * 8 = 128 rows
    const int c0 = (tid & 7) * 8;    // 8 groups * 8 = 64 cols
    const int sw = ((r0 >> 3) & 7) << 2;

    unsigned long long acc[8][4];
#pragma unroll
    for (int i = 0; i < 8; ++i)
#pragma unroll
        for (int j = 0; j < 4; ++j) acc[i][j] = 0ull;

    // ---- GEMM1: P = Q_t @ M_t (A via float4 k-chunks) ----
#pragma unroll 2
    for (int k0 = 0; k0 < 64; k0 += 4) {
        float a[8][4];
#pragma unroll
        for (int i = 0; i < 8; ++i)
            *(float4*)a[i] = *(const float4*)&sQ[(r0 + i) * 64 + (k0 ^ sw)];
#pragma unroll
        for (int j = 0; j < 4; ++j) {
            const ulonglong2 b01 = *(const ulonglong2*)&sMS[(k0 + j) * 64 + c0];
            const ulonglong2 b23 = *(const ulonglong2*)&sMS[(k0 + j) * 64 + c0 + 4];
            const unsigned long long pb[4] = {b01.x, b01.y, b23.x, b23.y};
#pragma unroll
            for (int i = 0; i < 8; ++i) {
                const unsigned long long pa = bcast2(a[i][j]);
                f2(acc[i][0], pa, pb[0]); f2(acc[i][1], pa, pb[1]);
                f2(acc[i][2], pa, pb[2]); f2(acc[i][3], pa, pb[3]);
            }
        }
    }

    // prefetch S while GEMM1 drains (writes gated by the sync below)
    float4 sreg[8];
#pragma unroll
    for (int j = 0; j < 8; ++j)
        sreg[j] = ((const float4*)g_S)[tid + j * 128];

    __syncthreads();   // all sQ/sMS reads complete

    // store P swizzled into sQ; store S into sMS
#pragma unroll
    for (int i = 0; i < 8; ++i) {
        float4 p0, p1;
        *(ulonglong2*)&p0 = make_ulonglong2(acc[i][0], acc[i][1]);
        *(ulonglong2*)&p1 = make_ulonglong2(acc[i][2], acc[i][3]);
        const int row = r0 + i;
        *(float4*)&sQ[row * 64 + (c0 ^ sw)]       = p0;
        *(float4*)&sQ[row * 64 + ((c0 + 4) ^ sw)] = p1;
    }
#pragma unroll
    for (int j = 0; j < 8; ++j)
        ((float4*)sMS)[tid + j * 128] = sreg[j];
    __syncthreads();

    // ---- GEMM2: out = P @ S ----
#pragma unroll
    for (int i = 0; i < 8; ++i)
#pragma unroll
        for (int j = 0; j < 4; ++j) acc[i][j] = 0ull;

#pragma unroll 2
    for (int k0 = 0; k0 < 64; k0 += 4) {
        float a[8][4];
#pragma unroll
        for (int i = 0; i < 8; ++i)
            *(float4*)a[i] = *(const float4*)&sQ[(r0 + i) * 64 + (k0 ^ sw)];
#pragma unroll
        for (int j = 0; j < 4; ++j) {
            const ulonglong2 b01 = *(const ulonglong2*)&sMS[(k0 + j) * 64 + c0];
            const ulonglong2 b23 = *(const ulonglong2*)&sMS[(k0 + j) * 64 + c0 + 4];
            const unsigned long long pb[4] = {b01.x, b01.y, b23.x, b23.y};
#pragma unroll
            for (int i = 0; i < 8; ++i) {
                const unsigned long long pa = bcast2(a[i][j]);
                f2(acc[i][0], pa, pb[0]); f2(acc[i][1], pa, pb[1]);
                f2(acc[i][2], pa, pb[2]); f2(acc[i][3], pa, pb[3]);
            }
        }
    }

    float* outp = outg + t * (TRUNK * D);
#pragma unroll
    for (int i = 0; i < 8; ++i) {
        *(ulonglong2*)&outp[(r0 + i) * 64 + c0]     = make_ulonglong2(acc[i][0], acc[i][1]);
        *(ulonglong2*)&outp[(r0 + i) * 64 + c0 + 4] = make_ulonglong2(acc[i][2], acc[i][3]);
    }
}

#define SMEM_QO_BYTES ((8192 + 4096) * 4)        // 49152

extern "C" void kernel_launch(void* const* d_in, const int* in_sizes, int n_in,
                              void* d_out, int out_size) {
    const float* Q = (const float*)d_in[0];
    const float* K = (const float*)d_in[1];
    const float* V = (const float*)d_in[2];
    float* out = (float*)d_out;

    cudaFuncSetAttribute(kQO, cudaFuncAttributeMaxDynamicSharedMemorySize, SMEM_QO_BYTES);

    kA<<<T_TRUNKS, 128>>>(K, V);
    kB1<<<B1_BLOCKS, 256>>>();
    kB2<<<16, 256>>>();
    kQO<<<T_TRUNKS, 128, SMEM_QO_BYTES>>>(Q, out);
}

// round 9
// speedup vs baseline: 1.8515x; 1.1763x over previous
#include <cuda_runtime.h>
#include <cuda_bf16.h>
#include <cstdint>

// LinearAttentionTriton:
//   M_t = K_t^T V_t   (64x64 per trunk)     -- kA (SIMT, round-7, unchanged)
//   S   = sum_t M_t^T (64x64 global)        -- kB1/kB2 (deterministic)
//   out_t = (Q_t @ M_t) @ S                 -- kQO (mma.sync bf16 hi/lo split)
// N = 262144, D = 64, TRUNK = 128, T = 2048.

#define D 64
#define TRUNK 128
#define T_TRUNKS 2048
#define B1_BLOCKS 128

__device__ __align__(16) float g_S[D * D];
__device__ __align__(16) float g_part[T_TRUNKS * D * D];
__device__ __align__(16) float g_red[B1_BLOCKS * D * D];

// ---------------- f32x2 helpers (SIMT kernels) ----------------
__device__ __forceinline__ unsigned long long bcast2(float x) {
    unsigned long long r;
    asm("mov.b64 %0, {%1, %1};" : "=l"(r) : "f"(x));
    return r;
}
__device__ __forceinline__ void f2(unsigned long long& d,
                                   unsigned long long a,
                                   unsigned long long b) {
    asm("fma.rn.f32x2 %0, %1, %2, %0;" : "+l"(d) : "l"(a), "l"(b));
}
__device__ __forceinline__ void a2(unsigned long long& d, unsigned long long a) {
    asm("add.rn.f32x2 %0, %0, %1;" : "+l"(d) : "l"(a));
}

// ---------------- kA: M_t = K_t^T V_t (round-7, unchanged) ----------------
__global__ void __launch_bounds__(128, 5) kA(const float* __restrict__ Kg,
                                             const float* __restrict__ Vg) {
    __shared__ float sK[64 * 64];
    __shared__ float sV[64 * 64];

    const int tid = threadIdx.x;
    const long t = blockIdx.x;
    const int h  = tid >> 6;
    const int lt = tid & 63;
    const int d0 = (lt >> 3) * 8;
    const int e0 = (lt & 7) * 8;

    unsigned long long acc[8][4];
#pragma unroll
    for (int i = 0; i < 8; ++i)
#pragma unroll
        for (int j = 0; j < 4; ++j) acc[i][j] = 0ull;

#pragma unroll
    for (int s = 0; s < 2; ++s) {
        const float4* K4 = (const float4*)Kg + t * 2048 + s * 1024;
        const float4* V4 = (const float4*)Vg + t * 2048 + s * 1024;
#pragma unroll
        for (int i = tid; i < 1024; i += 128) {
            ((float4*)sK)[i] = K4[i];
            ((float4*)sV)[i] = V4[i];
        }
        __syncthreads();
        const int rbase = h * 32;
#pragma unroll 4
        for (int rr = 0; rr < 32; ++rr) {
            const int r = rbase + rr;
            const float4 a03 = *(const float4*)&sK[r * 64 + d0];
            const float4 a47 = *(const float4*)&sK[r * 64 + d0 + 4];
            const ulonglong2 b01 = *(const ulonglong2*)&sV[r * 64 + e0];
            const ulonglong2 b23 = *(const ulonglong2*)&sV[r * 64 + e0 + 4];
            const unsigned long long pb[4] = {b01.x, b01.y, b23.x, b23.y};
            const float av[8] = {a03.x, a03.y, a03.z, a03.w,
                                 a47.x, a47.y, a47.z, a47.w};
#pragma unroll
            for (int i = 0; i < 8; ++i) {
                const unsigned long long pa = bcast2(av[i]);
                f2(acc[i][0], pa, pb[0]); f2(acc[i][1], pa, pb[1]);
                f2(acc[i][2], pa, pb[2]); f2(acc[i][3], pa, pb[3]);
            }
        }
        __syncthreads();
    }

    if (h == 1) {
#pragma unroll
        for (int i = 0; i < 8; ++i) {
            *(ulonglong2*)&sK[(d0 + i) * 64 + e0]     = make_ulonglong2(acc[i][0], acc[i][1]);
            *(ulonglong2*)&sK[(d0 + i) * 64 + e0 + 4] = make_ulonglong2(acc[i][2], acc[i][3]);
        }
    }
    __syncthreads();
    if (h == 0) {
        float* dst = g_part + t * 4096;
#pragma unroll
        for (int i = 0; i < 8; ++i) {
            const ulonglong2 v0 = *(const ulonglong2*)&sK[(d0 + i) * 64 + e0];
            const ulonglong2 v1 = *(const ulonglong2*)&sK[(d0 + i) * 64 + e0 + 4];
            a2(acc[i][0], v0.x); a2(acc[i][1], v0.y);
            a2(acc[i][2], v1.x); a2(acc[i][3], v1.y);
            *(ulonglong2*)&dst[(d0 + i) * 64 + e0]     = make_ulonglong2(acc[i][0], acc[i][1]);
            *(ulonglong2*)&dst[(d0 + i) * 64 + e0 + 4] = make_ulonglong2(acc[i][2], acc[i][3]);
        }
    }
}

// ---------------- kB1/kB2 ----------------
__global__ void __launch_bounds__(256) kB1() {
    const int blk = blockIdx.x;
    const int tid = threadIdx.x;
    const float* src = g_part + (long)blk * 16 * 4096;
#pragma unroll
    for (int i = 0; i < 16; ++i) {
        const int x = tid + i * 256;
        float s = 0.0f;
#pragma unroll
        for (int tt = 0; tt < 16; ++tt) s += src[tt * 4096 + x];
        g_red[blk * 4096 + x] = s;
    }
}
__global__ void __launch_bounds__(256) kB2() {
    const int idx = blockIdx.x * 256 + threadIdx.x;
    const int d = idx & 63, e = idx >> 6;
    float s = 0.0f;
#pragma unroll 8
    for (int b = 0; b < B1_BLOCKS; ++b) s += g_red[b * 4096 + idx];
    g_S[d * 64 + e] = s;
}

// ---------------- kQO: mma.sync bf16 hi/lo split ----------------
// SMEM (bytes): Ah [128][72] bf16 @0 (18432), Al @18432, Bh [64][72] @36864 (9216), Bl @46080.
#define AH_OFF 0
#define AL_OFF 18432
#define BH_OFF 36864
#define BL_OFF 46080
#define QO_SMEM 55296
#define ASTR 72   // bf16 elements per A row (144 B; 16B-aligned, conflict-free ldmatrix)

__device__ __forceinline__ uint32_t smem_u32(const void* p) {
    uint32_t a;
    asm("{ .reg .u64 t; cvta.to.shared.u64 t, %1; cvt.u32.u64 %0, t; }"
        : "=r"(a) : "l"(p));
    return a;
}

#define LDSM_X4(r0, r1, r2, r3, a) \
    asm volatile("ldmatrix.sync.aligned.m8n8.x4.shared.b16 {%0,%1,%2,%3}, [%4];" \
                 : "=r"(r0), "=r"(r1), "=r"(r2), "=r"(r3) : "r"(a))
#define LDSM_X2(r0, r1, a) \
    asm volatile("ldmatrix.sync.aligned.m8n8.x2.shared.b16 {%0,%1}, [%2];" \
                 : "=r"(r0), "=r"(r1) : "r"(a))
#define MMA16816(d, a, b) \
    asm volatile("mma.sync.aligned.m16n8k16.row.col.f32.bf16.bf16.f32 " \
                 "{%0,%1,%2,%3}, {%4,%5,%6,%7}, {%8,%9}, {%0,%1,%2,%3};" \
                 : "+f"((d)[0]), "+f"((d)[1]), "+f"((d)[2]), "+f"((d)[3]) \
                 : "r"((a)[0]), "r"((a)[1]), "r"((a)[2]), "r"((a)[3]), \
                   "r"((b)[0]), "r"((b)[1]))

__device__ __forceinline__ void split_pair(char* ph, char* pl, float x, float y) {
    __nv_bfloat16 hx = __float2bfloat16_rn(x), hy = __float2bfloat16_rn(y);
    __nv_bfloat162 h; h.x = hx; h.y = hy;
    __nv_bfloat162 l;
    l.x = __float2bfloat16_rn(x - __bfloat162float(hx));
    l.y = __float2bfloat16_rn(y - __bfloat162float(hy));
    *(__nv_bfloat162*)ph = h;
    *(__nv_bfloat162*)pl = l;
}

// one GEMM pass: acc += Abf(128x64) @ Bbf(64x64), 3 split products
__device__ __forceinline__ void gemm_bf16(uint32_t sb, float acc[2][8][4],
                                          int lane, int wid) {
    const uint32_t aRowByte = (uint32_t)((wid * 32 + (lane & 15)) * (ASTR * 2));
    const uint32_t aColByte = (uint32_t)((lane >> 4) * 16);          // +0 / +16B (8 cols)
    const uint32_t bRowByte = (uint32_t)((lane & 7) * (ASTR * 2));
    const uint32_t bColByte = (uint32_t)(((lane >> 3) & 1) * 16);

#pragma unroll
    for (int k0 = 0; k0 < 64; k0 += 16) {
        const uint32_t kByte = (uint32_t)(k0 * 2);
        uint32_t bh[8][2], bl[8][2];
#pragma unroll
        for (int n = 0; n < 8; ++n) {
            const uint32_t ba = sb + BH_OFF + (uint32_t)(n * 8 * ASTR * 2)
                                + bRowByte + kByte + bColByte;
            LDSM_X2(bh[n][0], bh[n][1], ba);
            LDSM_X2(bl[n][0], bl[n][1], ba + (BL_OFF - BH_OFF));
        }
#pragma unroll
        for (int s = 0; s < 2; ++s) {
            const uint32_t aa = sb + AH_OFF + aRowByte + (uint32_t)(s * 16 * ASTR * 2)
                                + kByte + aColByte;
            uint32_t ah[4], al[4];
            LDSM_X4(ah[0], ah[1], ah[2], ah[3], aa);
            LDSM_X4(al[0], al[1], al[2], al[3], aa + (AL_OFF - AH_OFF));
#pragma unroll
            for (int n = 0; n < 8; ++n) {
                MMA16816(acc[s][n], ah, bh[n]);
                MMA16816(acc[s][n], ah, bl[n]);
                MMA16816(acc[s][n], al, bh[n]);
            }
        }
    }
}

__global__ void __launch_bounds__(128, 4) kQO(const float* __restrict__ Qg,
                                              float* __restrict__ outg) {
    extern __shared__ __align__(16) char sm[];
    const uint32_t sb = smem_u32(sm);
    const int tid = threadIdx.x, lane = tid & 31, wid = tid >> 5;
    const long t = blockIdx.x;

    // convert Q -> Ah/Al (row-major, stride ASTR)
    const float4* Q4 = (const float4*)Qg + t * 2048;
#pragma unroll
    for (int i = tid; i < 2048; i += 128) {
        const float4 v = Q4[i];
        const int row = i >> 4, col = (i & 15) << 2;
        const int off = row * (ASTR * 2) + col * 2;
        split_pair(sm + AH_OFF + off,     sm + AL_OFF + off,     v.x, v.y);
        split_pair(sm + AH_OFF + off + 4, sm + AL_OFF + off + 4, v.z, v.w);
    }
    // convert M^T -> Bh/Bl (rows = output col c, cols = k)
    const float4* M4 = (const float4*)g_part + t * 1024;
#pragma unroll
    for (int i = tid; i < 1024; i += 128) {
        const float4 v = M4[i];
        const int k = i >> 4, c = (i & 15) << 2;
        const float vv[4] = {v.x, v.y, v.z, v.w};
#pragma unroll
        for (int j = 0; j < 4; ++j) {
            const int off = (c + j) * (ASTR * 2) + k * 2;
            __nv_bfloat16 h = __float2bfloat16_rn(vv[j]);
            *(__nv_bfloat16*)(sm + BH_OFF + off) = h;
            *(__nv_bfloat16*)(sm + BL_OFF + off) =
                __float2bfloat16_rn(vv[j] - __bfloat162float(h));
        }
    }
    __syncthreads();

    float acc[2][8][4];
#pragma unroll
    for (int s = 0; s < 2; ++s)
#pragma unroll
        for (int n = 0; n < 8; ++n)
#pragma unroll
            for (int j = 0; j < 4; ++j) acc[s][n][j] = 0.0f;

    // GEMM1: P = Q @ M
    gemm_bf16(sb, acc, lane, wid);
    __syncthreads();   // all A/B reads complete

    // P fragments -> Ah/Al (next A operand); convert S^T -> Bh/Bl
    const int g = lane >> 2, tc = lane & 3;
#pragma unroll
    for (int s = 0; s < 2; ++s)
#pragma unroll
        for (int n = 0; n < 8; ++n) {
            const int col = n * 8 + tc * 2;
            const int row1 = wid * 32 + s * 16 + g;
            const int off1 = row1 * (ASTR * 2) + col * 2;
            const int off2 = off1 + 8 * (ASTR * 2);
            split_pair(sm + AH_OFF + off1, sm + AL_OFF + off1,
                       acc[s][n][0], acc[s][n][1]);
            split_pair(sm + AH_OFF + off2, sm + AL_OFF + off2,
                       acc[s][n][2], acc[s][n][3]);
        }
#pragma unroll
    for (int i = tid; i < 1024; i += 128) {
        const float4 v = ((const float4*)g_S)[i];
        const int k = i >> 4, c = (i & 15) << 2;
        const float vv[4] = {v.x, v.y, v.z, v.w};
#pragma unroll
        for (int j = 0; j < 4; ++j) {
            const int off = (c + j) * (ASTR * 2) + k * 2;
            __nv_bfloat16 h = __float2bfloat16_rn(vv[j]);
            *(__nv_bfloat16*)(sm + BH_OFF + off) = h;
            *(__nv_bfloat16*)(sm + BL_OFF + off) =
                __float2bfloat16_rn(vv[j] - __bfloat162float(h));
        }
    }
    __syncthreads();

#pragma unroll
    for (int s = 0; s < 2; ++s)
#pragma unroll
        for (int n = 0; n < 8; ++n)
#pragma unroll
            for (int j = 0; j < 4; ++j) acc[s][n][j] = 0.0f;

    // GEMM2: out = P @ S
    gemm_bf16(sb, acc, lane, wid);

    // epilogue
    float* outp = outg + t * (TRUNK * D);
#pragma unroll
    for (int s = 0; s < 2; ++s)
#pragma unroll
        for (int n = 0; n < 8; ++n) {
            const int col = n * 8 + tc * 2;
            const int row1 = wid * 32 + s * 16 + g;
            float2 v0; v0.x = acc[s][n][0]; v0.y = acc[s][n][1];
            float2 v1; v1.x = acc[s][n][2]; v1.y = acc[s][n][3];
            *(float2*)&outp[row1 * 64 + col]       = v0;
            *(float2*)&outp[(row1 + 8) * 64 + col] = v1;
        }
}

extern "C" void kernel_launch(void* const* d_in, const int* in_sizes, int n_in,
                              void* d_out, int out_size) {
    const float* Q = (const float*)d_in[0];
    const float* K = (const float*)d_in[1];
    const float* V = (const float*)d_in[2];
    float* out = (float*)d_out;

    cudaFuncSetAttribute(kQO, cudaFuncAttributeMaxDynamicSharedMemorySize, QO_SMEM);

    kA<<<T_TRUNKS, 128>>>(K, V);
    kB1<<<B1_BLOCKS, 256>>>();
    kB2<<<16, 256>>>();
    kQO<<<T_TRUNKS, 128, QO_SMEM>>>(Q, out);
}

// round 10
// speedup vs baseline: 2.3691x; 1.2796x over previous
#include <cuda_runtime.h>
#include <cuda_bf16.h>
#include <cstdint>

// LinearAttentionTriton (all-HMMA):
//   g_part_t[e*64+d] = M_t[d][e] = sum_r K[r][d] V[r][e]   -- kA (mma.sync bf16 hi/lo)
//   g_S[e*64+c]      = S[c][e],  S = sum_t M_t^T           -- kB1/kB2 (deterministic)
//   out_t = (Q_t @ M_t) @ S                                 -- kQO (mma.sync bf16 hi/lo)
// N = 262144, D = 64, TRUNK = 128, T = 2048.

#define D 64
#define TRUNK 128
#define T_TRUNKS 2048
#define B1_BLOCKS 128

__device__ __align__(16) float g_S[D * D];
__device__ __align__(16) float g_part[T_TRUNKS * D * D];
__device__ __align__(16) float g_red[B1_BLOCKS * D * D];

// ---------------- common helpers ----------------
__device__ __forceinline__ uint32_t smem_u32(const void* p) {
    uint32_t a;
    asm("{ .reg .u64 t; cvta.to.shared.u64 t, %1; cvt.u32.u64 %0, t; }"
        : "=r"(a) : "l"(p));
    return a;
}
#define LDSM_X4(r0, r1, r2, r3, a) \
    asm volatile("ldmatrix.sync.aligned.m8n8.x4.shared.b16 {%0,%1,%2,%3}, [%4];" \
                 : "=r"(r0), "=r"(r1), "=r"(r2), "=r"(r3) : "r"(a))
#define LDSM_X2(r0, r1, a) \
    asm volatile("ldmatrix.sync.aligned.m8n8.x2.shared.b16 {%0,%1}, [%2];" \
                 : "=r"(r0), "=r"(r1) : "r"(a))
#define LDSM_X4_T(r0, r1, r2, r3, a) \
    asm volatile("ldmatrix.sync.aligned.m8n8.x4.trans.shared.b16 {%0,%1,%2,%3}, [%4];" \
                 : "=r"(r0), "=r"(r1), "=r"(r2), "=r"(r3) : "r"(a))
#define LDSM_X2_T(r0, r1, a) \
    asm volatile("ldmatrix.sync.aligned.m8n8.x2.trans.shared.b16 {%0,%1}, [%2];" \
                 : "=r"(r0), "=r"(r1) : "r"(a))
#define MMA16816(d, a, b) \
    asm volatile("mma.sync.aligned.m16n8k16.row.col.f32.bf16.bf16.f32 " \
                 "{%0,%1,%2,%3}, {%4,%5,%6,%7}, {%8,%9}, {%0,%1,%2,%3};" \
                 : "+f"((d)[0]), "+f"((d)[1]), "+f"((d)[2]), "+f"((d)[3]) \
                 : "r"((a)[0]), "r"((a)[1]), "r"((a)[2]), "r"((a)[3]), \
                   "r"((b)[0]), "r"((b)[1]))

__device__ __forceinline__ void split_pair(char* ph, char* pl, float x, float y) {
    __nv_bfloat16 hx = __float2bfloat16_rn(x), hy = __float2bfloat16_rn(y);
    __nv_bfloat162 h; h.x = hx; h.y = hy;
    __nv_bfloat162 l;
    l.x = __float2bfloat16_rn(x - __bfloat162float(hx));
    l.y = __float2bfloat16_rn(y - __bfloat162float(hy));
    *(__nv_bfloat162*)ph = h;
    *(__nv_bfloat162*)pl = l;
}

// ---------------- kA: M^T via mma.sync, both operands ldmatrix.trans ----------------
// out[m=e][n=d] = sum_r V[r][e] K[r][d]  (A = V^T, B = K^T; K,V stored natural [r][.])
// smem: Kh, Kl, Vh, Vl each [128][72] bf16 (144 B rows). 72 KB -> 3 CTAs/SM.
#define KA_STRB 144
#define KA_KH 0
#define KA_KL 18432
#define KA_VH 36864
#define KA_VL 55296
#define KA_SMEM 73728

__global__ void __launch_bounds__(128) kA(const float* __restrict__ Kg,
                                          const float* __restrict__ Vg) {
    extern __shared__ __align__(16) char sm[];
    const uint32_t sb = smem_u32(sm);
    const int tid = threadIdx.x, lane = tid & 31, wid = tid >> 5;
    const long t = blockIdx.x;

    const float4* K4 = (const float4*)Kg + t * 2048;
    const float4* V4 = (const float4*)Vg + t * 2048;
#pragma unroll
    for (int i = tid; i < 2048; i += 128) {
        const int off = (i >> 4) * KA_STRB + ((i & 15) << 3);  // row*144 + col*2
        const float4 kv = K4[i];
        split_pair(sm + KA_KH + off,     sm + KA_KL + off,     kv.x, kv.y);
        split_pair(sm + KA_KH + off + 4, sm + KA_KL + off + 4, kv.z, kv.w);
        const float4 vv = V4[i];
        split_pair(sm + KA_VH + off,     sm + KA_VL + off,     vv.x, vv.y);
        split_pair(sm + KA_VH + off + 4, sm + KA_VL + off + 4, vv.z, vv.w);
    }
    __syncthreads();

    float acc[8][4];
#pragma unroll
    for (int n = 0; n < 8; ++n)
#pragma unroll
        for (int j = 0; j < 4; ++j) acc[n][j] = 0.0f;

    const int m0 = wid * 16;
    // A (trans x4): lane l -> &V[k0 + (l&7) + ((l>>4)<<3)][m0 + ((l>>3)&1)*8]
    const uint32_t aBase = sb + KA_VH
        + (uint32_t)(((lane & 7) + ((lane >> 4) << 3)) * KA_STRB)
        + (uint32_t)((m0 + ((lane >> 3) & 1) * 8) * 2);
    // B (trans x2): lane l (0-15) -> &K[k0 + (l&7) + ((l>>3)&1)*8][n0]
    const uint32_t bBase = sb + KA_KH
        + (uint32_t)(((lane & 7) + ((lane >> 3) & 1) * 8) * KA_STRB);

#pragma unroll
    for (int k0 = 0; k0 < 128; k0 += 16) {
        uint32_t ah[4], al[4];
        const uint32_t aa = aBase + (uint32_t)(k0 * KA_STRB);
        LDSM_X4_T(ah[0], ah[1], ah[2], ah[3], aa);
        LDSM_X4_T(al[0], al[1], al[2], al[3], aa + (KA_VL - KA_VH));
#pragma unroll
        for (int n = 0; n < 8; ++n) {
            uint32_t bh[2], bl[2];
            const uint32_t ba = bBase + (uint32_t)(k0 * KA_STRB) + (uint32_t)(n * 16);
            LDSM_X2_T(bh[0], bh[1], ba);
            LDSM_X2_T(bl[0], bl[1], ba + (KA_KL - KA_KH));
            MMA16816(acc[n], ah, bh);
            MMA16816(acc[n], ah, bl);
            MMA16816(acc[n], al, bh);
        }
    }

    // epilogue: fp32 M^T rows e = m0+g (+8), cols d = n*8 + 2*tc
    float* dst = g_part + t * 4096;
    const int g = lane >> 2, tc = lane & 3;
#pragma unroll
    for (int n = 0; n < 8; ++n) {
        const int col = n * 8 + tc * 2;
        float2 v0; v0.x = acc[n][0]; v0.y = acc[n][1];
        float2 v1; v1.x = acc[n][2]; v1.y = acc[n][3];
        *(float2*)&dst[(m0 + g) * 64 + col]     = v0;
        *(float2*)&dst[(m0 + g + 8) * 64 + col] = v1;
    }
}

// ---------------- kB1/kB2 ----------------
__global__ void __launch_bounds__(256) kB1() {
    const int blk = blockIdx.x;
    const int tid = threadIdx.x;
    const float* src = g_part + (long)blk * 16 * 4096;
#pragma unroll
    for (int i = 0; i < 16; ++i) {
        const int x = tid + i * 256;
        float s = 0.0f;
#pragma unroll
        for (int tt = 0; tt < 16; ++tt) s += src[tt * 4096 + x];
        g_red[blk * 4096 + x] = s;
    }
}
// g_part rows hold M^T => sum over t at x = c*64+e equals S[c][e].
// Store S transposed: g_S[e*64+c] = S[c][e] (natural B rows for kQO GEMM2).
__global__ void __launch_bounds__(256) kB2() {
    const int idx = blockIdx.x * 256 + threadIdx.x;   // idx = c*64 + e
    float s = 0.0f;
#pragma unroll 8
    for (int b = 0; b < B1_BLOCKS; ++b) s += g_red[b * 4096 + idx];
    const int c = idx >> 6, e = idx & 63;
    g_S[e * 64 + c] = s;
}

// ---------------- kQO: mma.sync bf16 hi/lo split ----------------
#define AH_OFF 0
#define AL_OFF 18432
#define BH_OFF 36864
#define BL_OFF 46080
#define QO_SMEM 55296
#define ASTR 72

// one GEMM pass: acc += Abf(128x64) @ Bbf(64x64), 3 split products
__device__ __forceinline__ void gemm_bf16(uint32_t sb, float acc[2][8][4],
                                          int lane, int wid) {
    const uint32_t aRowByte = (uint32_t)((wid * 32 + (lane & 15)) * (ASTR * 2));
    const uint32_t aColByte = (uint32_t)((lane >> 4) * 16);
    const uint32_t bRowByte = (uint32_t)((lane & 7) * (ASTR * 2));
    const uint32_t bColByte = (uint32_t)(((lane >> 3) & 1) * 16);

#pragma unroll
    for (int k0 = 0; k0 < 64; k0 += 16) {
        const uint32_t kByte = (uint32_t)(k0 * 2);
        uint32_t bh[8][2], bl[8][2];
#pragma unroll
        for (int n = 0; n < 8; ++n) {
            const uint32_t ba = sb + BH_OFF + (uint32_t)(n * 8 * ASTR * 2)
                                + bRowByte + kByte + bColByte;
            LDSM_X2(bh[n][0], bh[n][1], ba);
            LDSM_X2(bl[n][0], bl[n][1], ba + (BL_OFF - BH_OFF));
        }
#pragma unroll
        for (int s = 0; s < 2; ++s) {
            const uint32_t aa = sb + AH_OFF + aRowByte + (uint32_t)(s * 16 * ASTR * 2)
                                + kByte + aColByte;
            uint32_t ah[4], al[4];
            LDSM_X4(ah[0], ah[1], ah[2], ah[3], aa);
            LDSM_X4(al[0], al[1], al[2], al[3], aa + (AL_OFF - AH_OFF));
#pragma unroll
            for (int n = 0; n < 8; ++n) {
                MMA16816(acc[s][n], ah, bh[n]);
                MMA16816(acc[s][n], ah, bl[n]);
                MMA16816(acc[s][n], al, bh[n]);
            }
        }
    }
}

__global__ void __launch_bounds__(128, 4) kQO(const float* __restrict__ Qg,
                                              float* __restrict__ outg) {
    extern __shared__ __align__(16) char sm[];
    const uint32_t sb = smem_u32(sm);
    const int tid = threadIdx.x, lane = tid & 31, wid = tid >> 5;
    const long t = blockIdx.x;

    // Q -> Ah/Al (natural rows)
    const float4* Q4 = (const float4*)Qg + t * 2048;
#pragma unroll
    for (int i = tid; i < 2048; i += 128) {
        const float4 v = Q4[i];
        const int off = (i >> 4) * (ASTR * 2) + ((i & 15) << 3);
        split_pair(sm + AH_OFF + off,     sm + AL_OFF + off,     v.x, v.y);
        split_pair(sm + AH_OFF + off + 4, sm + AL_OFF + off + 4, v.z, v.w);
    }
    // M^T rows (g_part row c = M[.][c]) -> Bh/Bl, natural copy-convert
    const float4* M4 = (const float4*)g_part + t * 1024;
#pragma unroll
    for (int i = tid; i < 1024; i += 128) {
        const float4 v = M4[i];
        const int off = (i >> 4) * (ASTR * 2) + ((i & 15) << 3);
        split_pair(sm + BH_OFF + off,     sm + BL_OFF + off,     v.x, v.y);
        split_pair(sm + BH_OFF + off + 4, sm + BL_OFF + off + 4, v.z, v.w);
    }
    __syncthreads();

    float acc[2][8][4];
#pragma unroll
    for (int s = 0; s < 2; ++s)
#pragma unroll
        for (int n = 0; n < 8; ++n)
#pragma unroll
            for (int j = 0; j < 4; ++j) acc[s][n][j] = 0.0f;

    // GEMM1: P = Q @ M
    gemm_bf16(sb, acc, lane, wid);
    __syncthreads();

    // P fragments -> Ah/Al; S^T rows (g_S row e = S[.][e]) -> Bh/Bl natural
    const int g = lane >> 2, tc = lane & 3;
#pragma unroll
    for (int s = 0; s < 2; ++s)
#pragma unroll
        for (int n = 0; n < 8; ++n) {
            const int col = n * 8 + tc * 2;
            const int row1 = wid * 32 + s * 16 + g;
            const int off1 = row1 * (ASTR * 2) + col * 2;
            const int off2 = off1 + 8 * (ASTR * 2);
            split_pair(sm + AH_OFF + off1, sm + AL_OFF + off1,
                       acc[s][n][0], acc[s][n][1]);
            split_pair(sm + AH_OFF + off2, sm + AL_OFF + off2,
                       acc[s][n][2], acc[s][n][3]);
        }
#pragma unroll
    for (int i = tid; i < 1024; i += 128) {
        const float4 v = ((const float4*)g_S)[i];
        const int off = (i >> 4) * (ASTR * 2) + ((i & 15) << 3);
        split_pair(sm + BH_OFF + off,     sm + BL_OFF + off,     v.x, v.y);
        split_pair(sm + BH_OFF + off + 4, sm + BL_OFF + off + 4, v.z, v.w);
    }
    __syncthreads();

#pragma unroll
    for (int s = 0; s < 2; ++s)
#pragma unroll
        for (int n = 0; n < 8; ++n)
#pragma unroll
            for (int j = 0; j < 4; ++j) acc[s][n][j] = 0.0f;

    // GEMM2: out = P @ S
    gemm_bf16(sb, acc, lane, wid);

    float* outp = outg + t * (TRUNK * D);
#pragma unroll
    for (int s = 0; s < 2; ++s)
#pragma unroll
        for (int n = 0; n < 8; ++n) {
            const int col = n * 8 + tc * 2;
            const int row1 = wid * 32 + s * 16 + g;
            float2 v0; v0.x = acc[s][n][0]; v0.y = acc[s][n][1];
            float2 v1; v1.x = acc[s][n][2]; v1.y = acc[s][n][3];
            *(float2*)&outp[row1 * 64 + col]       = v0;
            *(float2*)&outp[(row1 + 8) * 64 + col] = v1;
        }
}

extern "C" void kernel_launch(void* const* d_in, const int* in_sizes, int n_in,
                              void* d_out, int out_size) {
    const float* Q = (const float*)d_in[0];
    const float* K = (const float*)d_in[1];
    const float* V = (const float*)d_in[2];
    float* out = (float*)d_out;

    cudaFuncSetAttribute(kA,  cudaFuncAttributeMaxDynamicSharedMemorySize, KA_SMEM);
    cudaFuncSetAttribute(kQO, cudaFuncAttributeMaxDynamicSharedMemorySize, QO_SMEM);

    kA<<<T_TRUNKS, 128, KA_SMEM>>>(K, V);
    kB1<<<B1_BLOCKS, 256>>>();
    kB2<<<16, 256>>>();
    kQO<<<T_TRUNKS, 128, QO_SMEM>>>(Q, out);
}